// round 3
// baseline (speedup 1.0000x reference)
#include <cuda_runtime.h>
#include <math.h>
#include <stdint.h>

// Problem-size maxima (fixed benchmark shape B=64, P=24564, C=81, T=50)
#define BMAX 64
#define PMAX 24564
#define TMAX 50

// ---------------- scratch (__device__ globals; no allocation allowed) -------
__device__ float               g_bt_ov [BMAX * PMAX];   // best truth overlap per prior
__device__ int                 g_bt_idx[BMAX * PMAX];   // best truth index per prior
__device__ float               g_mine  [BMAX * PMAX];   // loss_mine = pos ? 0 : ce
__device__ unsigned long long  g_best_enc[BMAX * TMAX]; // per-gt best prior (encoded)
__device__ int                 g_num_pos[BMAX];
__device__ double              g_loss_l;
__device__ double              g_loss_c;

// ---------------- init ------------------------------------------------------
__global__ void k_init(int B, int T) {
    int i = blockIdx.x * blockDim.x + threadIdx.x;
    if (i == 0) { g_loss_l = 0.0; g_loss_c = 0.0; }
    if (i < B) g_num_pos[i] = 0;
    if (i < B * T) g_best_enc[i] = 0ull;
}

// ---------------- matching: per-prior best-truth + per-gt best-prior --------
__global__ void k_match(const float* __restrict__ priors,
                        const float* __restrict__ tboxes,
                        int P, int T) {
    int b = blockIdx.y;
    __shared__ float4 s_t[TMAX];
    __shared__ float  s_ar[TMAX];
    __shared__ unsigned long long s_best[TMAX];
    int tid = threadIdx.x;
    if (tid < T) {
        const float* tb = tboxes + ((size_t)b * T + tid) * 4;
        float x1 = tb[0], y1 = tb[1], x2 = tb[2], y2 = tb[3];
        s_t[tid] = make_float4(x1, y1, x2, y2);
        s_ar[tid] = (x2 - x1) * (y2 - y1);
        s_best[tid] = 0ull;
    }
    __syncthreads();

    int p = blockIdx.x * blockDim.x + tid;
    bool valid = (p < P);
    float px1, py1, px2, py2, areaB;
    if (valid) {
        float4 pr = ((const float4*)priors)[p];
        px1 = pr.x - pr.z * 0.5f; py1 = pr.y - pr.w * 0.5f;
        px2 = pr.x + pr.z * 0.5f; py2 = pr.y + pr.w * 0.5f;
        areaB = (px2 - px1) * (py2 - py1);
    } else {
        px1 = 3e9f; py1 = 3e9f; px2 = 3e9f; py2 = 3e9f; areaB = 0.f;
    }

    float best = -1.0f; int bestt = 0;
    int lane = tid & 31;
    for (int t = 0; t < T; t++) {
        float4 g = s_t[t];
        float ix = fminf(g.z, px2) - fmaxf(g.x, px1);
        float iy = fminf(g.w, py2) - fmaxf(g.y, py1);
        float inter = fmaxf(ix, 0.f) * fmaxf(iy, 0.f);
        float ov = inter / (s_ar[t] + areaB - inter);   // exact div (matches ref ties)
        if (ov > best) { best = ov; bestt = t; }        // strict > : first-t ties
        unsigned bits = valid ? __float_as_uint(ov) : 0u;
        unsigned wmax = __reduce_max_sync(0xFFFFFFFFu, bits);
        unsigned bal  = __ballot_sync(0xFFFFFFFFu, bits == wmax);
        if (lane == (__ffs(bal) - 1)) {
            unsigned long long enc = (((unsigned long long)wmax) << 32) |
                                     (unsigned long long)(0xFFFFFFFFu - (unsigned)p);
            if (enc > s_best[t]) atomicMax(&s_best[t], enc);
        }
    }
    if (valid) {
        g_bt_ov [(size_t)b * P + p] = best;
        g_bt_idx[(size_t)b * P + p] = bestt;
    }
    __syncthreads();
    if (tid < T && s_best[tid]) atomicMax(&g_best_enc[b * T + tid], s_best[tid]);
}

// ---------------- force-match best prior of each gt (sequential last-wins) --
__global__ void k_force(int B, int P, int T) {
    int b = blockIdx.x * blockDim.x + threadIdx.x;
    if (b >= B) return;
    for (int t = 0; t < T; t++) {
        unsigned long long enc = g_best_enc[b * T + t];
        unsigned p = enc ? (0xFFFFFFFFu - (unsigned)(enc & 0xFFFFFFFFull)) : 0u;
        g_bt_ov [(size_t)b * P + p] = 2.0f;
        g_bt_idx[(size_t)b * P + p] = t;
    }
}

// ---------------- shared epilogue helpers -----------------------------------
__device__ __forceinline__ float sl1(float d) {
    float a = fabsf(d);
    return (a < 1.0f) ? 0.5f * d * d : a - 0.5f;
}

__device__ __forceinline__ void pos_epilogue(int bp, int P, int T, int ti, float ce,
                                             const float* __restrict__ loc,
                                             const float* __restrict__ priors,
                                             const float* __restrict__ tboxes) {
    int bq = bp / P, pq = bp % P;
    atomicAdd(&g_num_pos[bq], 1);
    atomicAdd(&g_loss_c, (double)ce);
    float4 ld = ((const float4*)loc)[bp];
    float4 pr = ((const float4*)priors)[pq];
    const float* tb = tboxes + ((size_t)bq * T + ti) * 4;
    float gx = ((tb[0] + tb[2]) * 0.5f - pr.x) / (0.1f * pr.z);
    float gy = ((tb[1] + tb[3]) * 0.5f - pr.y) / (0.1f * pr.w);
    float gw = logf((tb[2] - tb[0]) / pr.z) / 0.2f;
    float gh = logf((tb[3] - tb[1]) / pr.w) / 0.2f;
    float ll = sl1(ld.x - gx) + sl1(ld.y - gy) + sl1(ld.z - gw) + sl1(ld.w - gh);
    atomicAdd(&g_loss_l, (double)ll);
}

// ---------------- fast ce: C==81, 4 priors per warp, float4 streaming -------
__global__ void k_ce81(const float4* __restrict__ cf4,
                       const float* __restrict__ loc,
                       const float* __restrict__ priors,
                       const float* __restrict__ tboxes,
                       const int*   __restrict__ tlabels,
                       int B, int P, int T) {
    int warp = (int)((blockIdx.x * (size_t)blockDim.x + threadIdx.x) >> 5);
    int lane = threadIdx.x & 31;
    int bp0 = warp * 4;
    int BP = B * P;
    if (bp0 >= BP) return;

    // prefetch match results early (independent broadcast loads)
    float4 ov4 = *(const float4*)(g_bt_ov + bp0);
    int4   ix4 = *(const int4*)(g_bt_idx + bp0);

    // conf tile: 4 rows x 81 floats = exactly 81 float4s, base aligned (bp0%4==0)
    size_t t0 = (size_t)warp * 81;
    float4 v0 = cf4[t0 + lane];
    float4 v1 = cf4[t0 + 32 + lane];
    float4 v2 = make_float4(0.f, 0.f, 0.f, 0.f);
    if (lane < 17) v2 = cf4[t0 + 64 + lane];

    // labels + conf_t (small table, L1/L2 resident; overlapped with conf loads)
    int   ti[4]  = {ix4.x, ix4.y, ix4.z, ix4.w};
    float ovv[4] = {ov4.x, ov4.y, ov4.z, ov4.w};
    int ct[4];
    #pragma unroll
    for (int q = 0; q < 4; q++) {
        int bq = (bp0 + q) / P;
        int lab = tlabels[bq * T + ti[q]];
        ct[q] = (ovv[q] < 0.5f) ? 0 : (lab + 1);
    }

    // accumulate per-row sum of exps (range-specialized: reg0 spans rows 0/1,
    // reg1 spans rows 1/2/3, reg2 is entirely row 3)
    float s0 = 0.f, s1 = 0.f, s2 = 0.f, s3 = 0.f;
    {
        int f = 4 * lane;                   // [0,127]
        float e[4] = {__expf(v0.x), __expf(v0.y), __expf(v0.z), __expf(v0.w)};
        #pragma unroll
        for (int j = 0; j < 4; j++) { if (f + j < 81) s0 += e[j]; else s1 += e[j]; }
    }
    {
        int f = 128 + 4 * lane;             // [128,255]
        float e[4] = {__expf(v1.x), __expf(v1.y), __expf(v1.z), __expf(v1.w)};
        #pragma unroll
        for (int j = 0; j < 4; j++) {
            int g = f + j;
            if (g < 162) s1 += e[j];
            else if (g < 243) s2 += e[j];
            else s3 += e[j];
        }
    }
    if (lane < 17) {                        // f in [256,323] -> all row 3
        s3 += __expf(v2.x) + __expf(v2.y) + __expf(v2.z) + __expf(v2.w);
    }
    #pragma unroll
    for (int o = 16; o > 0; o >>= 1) {
        s0 += __shfl_xor_sync(0xFFFFFFFFu, s0, o);
        s1 += __shfl_xor_sync(0xFFFFFFFFu, s1, o);
        s2 += __shfl_xor_sync(0xFFFFFFFFu, s2, o);
        s3 += __shfl_xor_sync(0xFFFFFFFFu, s3, o);
    }
    float lse[4] = {__logf(s0), __logf(s1), __logf(s2), __logf(s3)};

    // target logit from registers (one shuffle per row; ct uniform across warp)
    float ce[4];
    #pragma unroll
    for (int q = 0; q < 4; q++) {
        int f = q * 81 + ct[q];
        int i = f >> 2, j = f & 3, r = i >> 5, src = i & 31;
        float4 vr = (r == 0) ? v0 : ((r == 1) ? v1 : v2);
        float comp = (j == 0) ? vr.x : ((j == 1) ? vr.y : ((j == 2) ? vr.z : vr.w));
        float tgt = __shfl_sync(0xFFFFFFFFu, comp, src);
        ce[q] = lse[q] - tgt;
    }

    if (lane == 0) {
        float4 mine;
        mine.x = (ct[0] > 0) ? 0.f : ce[0];
        mine.y = (ct[1] > 0) ? 0.f : ce[1];
        mine.z = (ct[2] > 0) ? 0.f : ce[2];
        mine.w = (ct[3] > 0) ? 0.f : ce[3];
        *(float4*)(g_mine + bp0) = mine;
        #pragma unroll
        for (int q = 0; q < 4; q++)
            if (ct[q] > 0) pos_epilogue(bp0 + q, P, T, ti[q], ce[q], loc, priors, tboxes);
    }
}

// ---------------- generic fallback ce (any C) -------------------------------
__global__ void k_ce_gen(const float* __restrict__ conf,
                         const float* __restrict__ loc,
                         const float* __restrict__ priors,
                         const float* __restrict__ tboxes,
                         const int*   __restrict__ tlabels,
                         int B, int P, int C, int T) {
    int wg = (int)((blockIdx.x * (size_t)blockDim.x + threadIdx.x) >> 5);
    int lane = threadIdx.x & 31;
    if (wg >= B * P) return;
    int b = wg / P, p = wg % P;
    size_t base = ((size_t)b * P + p) * (size_t)C;

    float m = -INFINITY;
    for (int c = lane; c < C; c += 32) m = fmaxf(m, conf[base + c]);
    #pragma unroll
    for (int o = 16; o > 0; o >>= 1) m = fmaxf(m, __shfl_xor_sync(0xFFFFFFFFu, m, o));
    float s = 0.f;
    for (int c = lane; c < C; c += 32) s += __expf(conf[base + c] - m);
    #pragma unroll
    for (int o = 16; o > 0; o >>= 1) s += __shfl_xor_sync(0xFFFFFFFFu, s, o);
    float lse = m + __logf(s);

    if (lane == 0) {
        size_t bp = (size_t)b * P + p;
        float ov = g_bt_ov[bp];
        int   ti = g_bt_idx[bp];
        int conf_t = (ov < 0.5f) ? 0 : (tlabels[b * T + ti] + 1);
        float ce = lse - conf[base + conf_t];
        bool pos = (conf_t > 0);
        g_mine[bp] = pos ? 0.0f : ce;
        if (pos) pos_epilogue((int)bp, P, T, ti, ce, loc, priors, tboxes);
    }
}

// ---------------- per-batch top-k sum via 8-bit MSB radix select ------------
#define SEL_THREADS 512
__global__ void k_select(int P) {
    int b = blockIdx.x;
    __shared__ unsigned s_cnt[256];
    __shared__ unsigned s_prefix;
    __shared__ int s_k;
    __shared__ double s_sum[SEL_THREADS];
    int tid = threadIdx.x;
    int lane = tid & 31;

    if (tid == 0) {
        int np = g_num_pos[b];
        int k = 3 * np;
        if (k > P - 1) k = P - 1;
        s_k = k;
        s_prefix = 0u;
    }
    __syncthreads();
    if (s_k <= 0) return;

    const float*  mine  = g_mine + (size_t)b * P;
    const float4* mine4 = (const float4*)mine;
    int P4 = P >> 2;
    int tail = P & 3;
    int iters = (P4 + SEL_THREADS - 1) / SEL_THREADS;

    for (int shift = 24; shift >= 0; shift -= 8) {
        if (tid < 256) s_cnt[tid] = 0;
        __syncthreads();
        unsigned pref = s_prefix;
        unsigned hm = (shift == 24) ? 0u : (0xFFFFFFFFu << (shift + 8));
        for (int it = 0; it < iters; it++) {
            int i = it * SEL_THREADS + tid;
            float4 v = make_float4(0.f, 0.f, 0.f, 0.f);
            bool valid = (i < P4);
            if (valid) v = mine4[i];
            unsigned u[4] = {__float_as_uint(v.x), __float_as_uint(v.y),
                             __float_as_uint(v.z), __float_as_uint(v.w)};
            #pragma unroll
            for (int j = 0; j < 4; j++) {
                bool ok = valid && ((u[j] & hm) == (pref & hm));
                unsigned bin = ok ? ((u[j] >> shift) & 255u) : 0xFFFFFFFFu;
                unsigned mm = __match_any_sync(0xFFFFFFFFu, bin);
                if (ok && lane == (__ffs(mm) - 1))
                    atomicAdd(&s_cnt[bin], (unsigned)__popc(mm));
            }
        }
        // scalar tail (P not multiple of 4)
        if (tid < tail) {
            unsigned v = __float_as_uint(mine[P4 * 4 + tid]);
            if ((v & hm) == (pref & hm))
                atomicAdd(&s_cnt[(v >> shift) & 255u], 1u);
        }
        __syncthreads();
        if (tid == 0) {
            int k = s_k;
            int cum = 0;
            unsigned g = 0;
            for (int d = 255; d >= 0; d--) {
                int c = (int)s_cnt[d];
                if (cum + c >= k) { g = (unsigned)d; s_k = k - cum; break; }
                cum += c;
            }
            s_prefix = pref | (g << shift);
        }
        __syncthreads();
    }

    unsigned thr = s_prefix;
    double sum = 0.0;
    for (int i = tid; i < P4; i += SEL_THREADS) {
        float4 v = mine4[i];
        if (__float_as_uint(v.x) > thr) sum += (double)v.x;
        if (__float_as_uint(v.y) > thr) sum += (double)v.y;
        if (__float_as_uint(v.z) > thr) sum += (double)v.z;
        if (__float_as_uint(v.w) > thr) sum += (double)v.w;
    }
    if (tid < tail) {
        float f = mine[P4 * 4 + tid];
        if (__float_as_uint(f) > thr) sum += (double)f;
    }
    if (tid == 0) sum += (double)s_k * (double)__uint_as_float(thr);
    s_sum[tid] = sum;
    __syncthreads();
    #pragma unroll
    for (int o = SEL_THREADS / 2; o > 0; o >>= 1) {
        if (tid < o) s_sum[tid] += s_sum[tid + o];
        __syncthreads();
    }
    if (tid == 0) atomicAdd(&g_loss_c, s_sum[0]);
}

// ---------------- finalize --------------------------------------------------
__global__ void k_final(float* out, int B) {
    if (threadIdx.x == 0 && blockIdx.x == 0) {
        int n = 0;
        for (int b = 0; b < B; b++) n += g_num_pos[b];
        double nn = (n < 1) ? 1.0 : (double)n;
        out[0] = (float)(g_loss_l / nn);
        out[1] = (float)(g_loss_c / nn);
    }
}

// ---------------- launch ----------------------------------------------------
extern "C" void kernel_launch(void* const* d_in, const int* in_sizes, int n_in,
                              void* d_out, int out_size) {
    const float* loc     = (const float*)d_in[0];
    const float* conf    = (const float*)d_in[1];
    const float* priors  = (const float*)d_in[2];
    const float* tboxes  = (const float*)d_in[3];
    const int*   tlabels = (const int*)  d_in[4];
    float* out = (float*)d_out;

    int P  = in_sizes[2] / 4;
    int B  = in_sizes[0] / (4 * P);
    int T  = in_sizes[4] / B;
    int C  = (int)((long long)in_sizes[1] / ((long long)B * P));
    int BP = B * P;

    // 1. init scratch accumulators
    {
        int n = B * T;
        if (n < B) n = B;
        if (n < 1) n = 1;
        k_init<<<(n + 255) / 256, 256>>>(B, T);
    }
    // 2. matching
    {
        dim3 grid((P + 255) / 256, B);
        k_match<<<grid, 256>>>(priors, tboxes, P, T);
    }
    // 3. force-match best prior per gt
    k_force<<<(B + 63) / 64, 64>>>(B, P, T);
    // 4. ce + smooth-L1
    if (C == 81 && (BP & 3) == 0) {
        long long warps = (BP + 3) / 4;
        long long blocks = (warps + 7) / 8;           // 8 warps / block
        k_ce81<<<(unsigned)blocks, 256>>>((const float4*)conf, loc, priors,
                                          tboxes, tlabels, B, P, T);
    } else {
        long long total_warps = (long long)BP;
        long long blocks = (total_warps + 7) / 8;
        k_ce_gen<<<(unsigned)blocks, 256>>>(conf, loc, priors, tboxes, tlabels,
                                            B, P, C, T);
    }
    // 5. per-batch hard-negative top-k sum
    k_select<<<B, SEL_THREADS>>>(P);
    // 6. finalize
    k_final<<<1, 32>>>(out, B);
}

// round 7
// speedup vs baseline: 1.4177x; 1.4177x over previous
#include <cuda_runtime.h>
#include <math.h>
#include <stdint.h>

// Problem-size maxima (fixed benchmark shape B=64, P=24564, C=81, T=50)
#define BMAX 64
#define PMAX 24564
#define TMAX 50
#define NSTRIPE 512

// ---------------- scratch (__device__ globals; no allocation allowed) -------
__device__ float               g_bt_ov [BMAX * PMAX];   // best truth overlap per prior
__device__ int                 g_bt_idx[BMAX * PMAX];   // best truth index per prior
__device__ float               g_mine  [BMAX * PMAX];   // loss_mine = pos ? 0 : ce
__device__ unsigned long long  g_best_enc[BMAX * TMAX]; // per-gt best prior (encoded)
__device__ int                 g_num_pos[BMAX];
__device__ double              g_lossl_part[NSTRIPE];   // striped accumulators
__device__ double              g_lossc_part[NSTRIPE];   // (kills same-addr FP64 atomics)

// ---------------- init ------------------------------------------------------
__global__ void k_init(int B, int T) {
    int i = blockIdx.x * blockDim.x + threadIdx.x;
    if (i < NSTRIPE) { g_lossl_part[i] = 0.0; g_lossc_part[i] = 0.0; }
    if (i < B) g_num_pos[i] = 0;
    if (i < B * T) g_best_enc[i] = 0ull;
}

// ---------------- matching: per-prior best-truth + per-gt best-prior --------
__global__ void k_match(const float* __restrict__ priors,
                        const float* __restrict__ tboxes,
                        int P, int T) {
    int b = blockIdx.y;
    __shared__ float4 s_t[TMAX];
    __shared__ float  s_ar[TMAX];
    __shared__ unsigned long long s_best[TMAX];
    int tid = threadIdx.x;
    if (tid < T) {
        const float* tb = tboxes + ((size_t)b * T + tid) * 4;
        float x1 = tb[0], y1 = tb[1], x2 = tb[2], y2 = tb[3];
        s_t[tid] = make_float4(x1, y1, x2, y2);
        s_ar[tid] = (x2 - x1) * (y2 - y1);
        s_best[tid] = 0ull;
    }
    __syncthreads();

    int p = blockIdx.x * blockDim.x + tid;
    bool valid = (p < P);
    float px1, py1, px2, py2, areaB;
    if (valid) {
        float4 pr = ((const float4*)priors)[p];
        px1 = pr.x - pr.z * 0.5f; py1 = pr.y - pr.w * 0.5f;
        px2 = pr.x + pr.z * 0.5f; py2 = pr.y + pr.w * 0.5f;
        areaB = (px2 - px1) * (py2 - py1);
    } else {
        px1 = 3e9f; py1 = 3e9f; px2 = 3e9f; py2 = 3e9f; areaB = 0.f;
    }

    float best = -1.0f; int bestt = 0;
    int lane = tid & 31;
    for (int t = 0; t < T; t++) {
        float4 g = s_t[t];
        float ix = fminf(g.z, px2) - fmaxf(g.x, px1);
        float iy = fminf(g.w, py2) - fmaxf(g.y, py1);
        float inter = fmaxf(ix, 0.f) * fmaxf(iy, 0.f);
        float ov = inter / (s_ar[t] + areaB - inter);   // exact div (matches ref ties)
        if (ov > best) { best = ov; bestt = t; }        // strict > : first-t ties
        unsigned bits = valid ? __float_as_uint(ov) : 0u;
        unsigned wmax = __reduce_max_sync(0xFFFFFFFFu, bits);
        unsigned bal  = __ballot_sync(0xFFFFFFFFu, bits == wmax);
        if (lane == (__ffs(bal) - 1)) {
            unsigned long long enc = (((unsigned long long)wmax) << 32) |
                                     (unsigned long long)(0xFFFFFFFFu - (unsigned)p);
            if (enc > s_best[t]) atomicMax(&s_best[t], enc);
        }
    }
    if (valid) {
        g_bt_ov [(size_t)b * P + p] = best;
        g_bt_idx[(size_t)b * P + p] = bestt;
    }
    __syncthreads();
    if (tid < T && s_best[tid]) atomicMax(&g_best_enc[b * T + tid], s_best[tid]);
}

// ---------------- force-match best prior of each gt (sequential last-wins) --
__global__ void k_force(int B, int P, int T) {
    int b = blockIdx.x * blockDim.x + threadIdx.x;
    if (b >= B) return;
    for (int t = 0; t < T; t++) {
        unsigned long long enc = g_best_enc[b * T + t];
        unsigned p = enc ? (0xFFFFFFFFu - (unsigned)(enc & 0xFFFFFFFFull)) : 0u;
        g_bt_ov [(size_t)b * P + p] = 2.0f;
        g_bt_idx[(size_t)b * P + p] = t;
    }
}

// ---------------- shared epilogue helpers -----------------------------------
__device__ __forceinline__ float sl1(float d) {
    float a = fabsf(d);
    return (a < 1.0f) ? 0.5f * d * d : a - 0.5f;
}

__device__ __forceinline__ void pos_epilogue(int bp, int P, int T, int ti, float ce,
                                             const float* __restrict__ loc,
                                             const float* __restrict__ priors,
                                             const float* __restrict__ tboxes) {
    int bq = bp / P, pq = bp % P;
    atomicAdd(&g_num_pos[bq], 1);
    atomicAdd(&g_lossc_part[bp & (NSTRIPE - 1)], (double)ce);   // striped: no serialization
    float4 ld = ((const float4*)loc)[bp];
    float4 pr = ((const float4*)priors)[pq];
    const float* tb = tboxes + ((size_t)bq * T + ti) * 4;
    float gx = ((tb[0] + tb[2]) * 0.5f - pr.x) / (0.1f * pr.z);
    float gy = ((tb[1] + tb[3]) * 0.5f - pr.y) / (0.1f * pr.w);
    float gw = logf((tb[2] - tb[0]) / pr.z) / 0.2f;
    float gh = logf((tb[3] - tb[1]) / pr.w) / 0.2f;
    float ll = sl1(ld.x - gx) + sl1(ld.y - gy) + sl1(ld.z - gw) + sl1(ld.w - gh);
    atomicAdd(&g_lossl_part[bp & (NSTRIPE - 1)], (double)ll);
}

// ---------------- fast ce: C==81, 4 priors per warp, float4 streaming -------
__global__ void k_ce81(const float4* __restrict__ cf4,
                       const float* __restrict__ loc,
                       const float* __restrict__ priors,
                       const float* __restrict__ tboxes,
                       const int*   __restrict__ tlabels,
                       int B, int P, int T) {
    int warp = (int)((blockIdx.x * (size_t)blockDim.x + threadIdx.x) >> 5);
    int lane = threadIdx.x & 31;
    int bp0 = warp * 4;
    int BP = B * P;
    if (bp0 >= BP) return;

    // prefetch match results early (independent broadcast loads)
    float4 ov4 = *(const float4*)(g_bt_ov + bp0);
    int4   ix4 = *(const int4*)(g_bt_idx + bp0);

    // conf tile: 4 rows x 81 floats = exactly 81 float4s, base aligned (bp0%4==0)
    size_t t0 = (size_t)warp * 81;
    float4 v0 = cf4[t0 + lane];
    float4 v1 = cf4[t0 + 32 + lane];
    float4 v2 = make_float4(0.f, 0.f, 0.f, 0.f);
    if (lane < 17) v2 = cf4[t0 + 64 + lane];

    int   ti[4]  = {ix4.x, ix4.y, ix4.z, ix4.w};
    float ovv[4] = {ov4.x, ov4.y, ov4.z, ov4.w};
    int ct[4];
    #pragma unroll
    for (int q = 0; q < 4; q++) {
        int bq = (bp0 + q) / P;
        int lab = tlabels[bq * T + ti[q]];
        ct[q] = (ovv[q] < 0.5f) ? 0 : (lab + 1);
    }

    // per-row sum of exps (range-specialized across the three float4 regs)
    float s0 = 0.f, s1 = 0.f, s2 = 0.f, s3 = 0.f;
    {
        int f = 4 * lane;                   // [0,127]
        float e[4] = {__expf(v0.x), __expf(v0.y), __expf(v0.z), __expf(v0.w)};
        #pragma unroll
        for (int j = 0; j < 4; j++) { if (f + j < 81) s0 += e[j]; else s1 += e[j]; }
    }
    {
        int f = 128 + 4 * lane;             // [128,255]
        float e[4] = {__expf(v1.x), __expf(v1.y), __expf(v1.z), __expf(v1.w)};
        #pragma unroll
        for (int j = 0; j < 4; j++) {
            int g = f + j;
            if (g < 162) s1 += e[j];
            else if (g < 243) s2 += e[j];
            else s3 += e[j];
        }
    }
    if (lane < 17) {                        // [256,323] -> all row 3
        s3 += __expf(v2.x) + __expf(v2.y) + __expf(v2.z) + __expf(v2.w);
    }
    #pragma unroll
    for (int o = 16; o > 0; o >>= 1) {
        s0 += __shfl_xor_sync(0xFFFFFFFFu, s0, o);
        s1 += __shfl_xor_sync(0xFFFFFFFFu, s1, o);
        s2 += __shfl_xor_sync(0xFFFFFFFFu, s2, o);
        s3 += __shfl_xor_sync(0xFFFFFFFFu, s3, o);
    }
    float lse[4] = {__logf(s0), __logf(s1), __logf(s2), __logf(s3)};

    // target logit from registers (one shuffle per row; ct uniform across warp)
    float ce[4];
    #pragma unroll
    for (int q = 0; q < 4; q++) {
        int f = q * 81 + ct[q];
        int i = f >> 2, j = f & 3, r = i >> 5, src = i & 31;
        float4 vr = (r == 0) ? v0 : ((r == 1) ? v1 : v2);
        float comp = (j == 0) ? vr.x : ((j == 1) ? vr.y : ((j == 2) ? vr.z : vr.w));
        float tgt = __shfl_sync(0xFFFFFFFFu, comp, src);
        ce[q] = lse[q] - tgt;
    }

    if (lane == 0) {
        float4 mine;
        mine.x = (ct[0] > 0) ? 0.f : ce[0];
        mine.y = (ct[1] > 0) ? 0.f : ce[1];
        mine.z = (ct[2] > 0) ? 0.f : ce[2];
        mine.w = (ct[3] > 0) ? 0.f : ce[3];
        *(float4*)(g_mine + bp0) = mine;
        #pragma unroll
        for (int q = 0; q < 4; q++)
            if (ct[q] > 0) pos_epilogue(bp0 + q, P, T, ti[q], ce[q], loc, priors, tboxes);
    }
}

// ---------------- generic fallback ce (any C) -------------------------------
__global__ void k_ce_gen(const float* __restrict__ conf,
                         const float* __restrict__ loc,
                         const float* __restrict__ priors,
                         const float* __restrict__ tboxes,
                         const int*   __restrict__ tlabels,
                         int B, int P, int C, int T) {
    int wg = (int)((blockIdx.x * (size_t)blockDim.x + threadIdx.x) >> 5);
    int lane = threadIdx.x & 31;
    if (wg >= B * P) return;
    int b = wg / P, p = wg % P;
    size_t base = ((size_t)b * P + p) * (size_t)C;

    float m = -INFINITY;
    for (int c = lane; c < C; c += 32) m = fmaxf(m, conf[base + c]);
    #pragma unroll
    for (int o = 16; o > 0; o >>= 1) m = fmaxf(m, __shfl_xor_sync(0xFFFFFFFFu, m, o));
    float s = 0.f;
    for (int c = lane; c < C; c += 32) s += __expf(conf[base + c] - m);
    #pragma unroll
    for (int o = 16; o > 0; o >>= 1) s += __shfl_xor_sync(0xFFFFFFFFu, s, o);
    float lse = m + __logf(s);

    if (lane == 0) {
        size_t bp = (size_t)b * P + p;
        float ov = g_bt_ov[bp];
        int   ti = g_bt_idx[bp];
        int conf_t = (ov < 0.5f) ? 0 : (tlabels[b * T + ti] + 1);
        float ce = lse - conf[base + conf_t];
        bool pos = (conf_t > 0);
        g_mine[bp] = pos ? 0.0f : ce;
        if (pos) pos_epilogue((int)bp, P, T, ti, ce, loc, priors, tboxes);
    }
}

// ---------------- per-batch top-k sum via 8-bit MSB radix select ------------
#define SEL_THREADS 512
__global__ void k_select(int P) {
    int b = blockIdx.x;
    __shared__ unsigned s_cnt[256];
    __shared__ unsigned s_prefix;
    __shared__ int s_k;
    __shared__ double s_sum[SEL_THREADS];
    int tid = threadIdx.x;
    int lane = tid & 31;

    if (tid == 0) {
        int np = g_num_pos[b];
        int k = 3 * np;
        if (k > P - 1) k = P - 1;
        s_k = k;
        s_prefix = 0u;
    }
    __syncthreads();
    if (s_k <= 0) return;

    const float*  mine  = g_mine + (size_t)b * P;
    const float4* mine4 = (const float4*)mine;
    int P4 = P >> 2;
    int tail = P & 3;
    int iters = (P4 + SEL_THREADS - 1) / SEL_THREADS;

    for (int shift = 24; shift >= 0; shift -= 8) {
        if (tid < 256) s_cnt[tid] = 0;
        __syncthreads();
        unsigned pref = s_prefix;
        unsigned hm = (shift == 24) ? 0u : (0xFFFFFFFFu << (shift + 8));
        for (int it = 0; it < iters; it++) {
            int i = it * SEL_THREADS + tid;
            float4 v = make_float4(0.f, 0.f, 0.f, 0.f);
            bool valid = (i < P4);
            if (valid) v = mine4[i];
            unsigned u[4] = {__float_as_uint(v.x), __float_as_uint(v.y),
                             __float_as_uint(v.z), __float_as_uint(v.w)};
            #pragma unroll
            for (int j = 0; j < 4; j++) {
                bool ok = valid && ((u[j] & hm) == (pref & hm));
                unsigned bin = ok ? ((u[j] >> shift) & 255u) : 0xFFFFFFFFu;
                unsigned mm = __match_any_sync(0xFFFFFFFFu, bin);
                if (ok && lane == (__ffs(mm) - 1))
                    atomicAdd(&s_cnt[bin], (unsigned)__popc(mm));
            }
        }
        if (tid < tail) {
            unsigned v = __float_as_uint(mine[P4 * 4 + tid]);
            if ((v & hm) == (pref & hm))
                atomicAdd(&s_cnt[(v >> shift) & 255u], 1u);
        }
        __syncthreads();
        if (tid == 0) {
            int k = s_k;
            int cum = 0;
            unsigned g = 0;
            for (int d = 255; d >= 0; d--) {
                int c = (int)s_cnt[d];
                if (cum + c >= k) { g = (unsigned)d; s_k = k - cum; break; }
                cum += c;
            }
            s_prefix = pref | (g << shift);
        }
        __syncthreads();
    }

    unsigned thr = s_prefix;
    double sum = 0.0;
    for (int i = tid; i < P4; i += SEL_THREADS) {
        float4 v = mine4[i];
        if (__float_as_uint(v.x) > thr) sum += (double)v.x;
        if (__float_as_uint(v.y) > thr) sum += (double)v.y;
        if (__float_as_uint(v.z) > thr) sum += (double)v.z;
        if (__float_as_uint(v.w) > thr) sum += (double)v.w;
    }
    if (tid < tail) {
        float f = mine[P4 * 4 + tid];
        if (__float_as_uint(f) > thr) sum += (double)f;
    }
    if (tid == 0) sum += (double)s_k * (double)__uint_as_float(thr);
    s_sum[tid] = sum;
    __syncthreads();
    #pragma unroll
    for (int o = SEL_THREADS / 2; o > 0; o >>= 1) {
        if (tid < o) s_sum[tid] += s_sum[tid + o];
        __syncthreads();
    }
    if (tid == 0) atomicAdd(&g_lossc_part[b & (NSTRIPE - 1)], s_sum[0]);
}

// ---------------- finalize (parallel reduce of striped partials) ------------
__global__ void k_final(float* out, int B) {
    __shared__ double s_l[NSTRIPE];
    __shared__ double s_c[NSTRIPE];
    __shared__ int    s_n[64];
    int tid = threadIdx.x;
    s_l[tid] = g_lossl_part[tid];
    s_c[tid] = g_lossc_part[tid];
    s_n[tid & 63] = 0;
    __syncthreads();
    if (tid < B) s_n[tid] = g_num_pos[tid];
    __syncthreads();
    #pragma unroll
    for (int o = NSTRIPE / 2; o > 0; o >>= 1) {
        if (tid < o) { s_l[tid] += s_l[tid + o]; s_c[tid] += s_c[tid + o]; }
        if (o <= 32 && tid < o) s_n[tid] += s_n[tid + o];
        __syncthreads();
    }
    if (tid == 0) {
        int n = s_n[0];
        double nn = (n < 1) ? 1.0 : (double)n;
        out[0] = (float)(s_l[0] / nn);
        out[1] = (float)(s_c[0] / nn);
    }
}

// ---------------- launch ----------------------------------------------------
extern "C" void kernel_launch(void* const* d_in, const int* in_sizes, int n_in,
                              void* d_out, int out_size) {
    const float* loc     = (const float*)d_in[0];
    const float* conf    = (const float*)d_in[1];
    const float* priors  = (const float*)d_in[2];
    const float* tboxes  = (const float*)d_in[3];
    const int*   tlabels = (const int*)  d_in[4];
    float* out = (float*)d_out;

    int P  = in_sizes[2] / 4;
    int B  = in_sizes[0] / (4 * P);
    int T  = in_sizes[4] / B;
    int C  = (int)((long long)in_sizes[1] / ((long long)B * P));
    int BP = B * P;

    // 1. init scratch accumulators
    {
        int n = B * T;
        if (n < NSTRIPE) n = NSTRIPE;
        k_init<<<(n + 255) / 256, 256>>>(B, T);
    }
    // 2. matching
    {
        dim3 grid((P + 255) / 256, B);
        k_match<<<grid, 256>>>(priors, tboxes, P, T);
    }
    // 3. force-match best prior per gt
    k_force<<<(B + 63) / 64, 64>>>(B, P, T);
    // 4. ce + smooth-L1
    if (C == 81 && (BP & 3) == 0) {
        long long warps = (BP + 3) / 4;
        long long blocks = (warps + 7) / 8;           // 8 warps / block
        k_ce81<<<(unsigned)blocks, 256>>>((const float4*)conf, loc, priors,
                                          tboxes, tlabels, B, P, T);
    } else {
        long long total_warps = (long long)BP;
        long long blocks = (total_warps + 7) / 8;
        k_ce_gen<<<(unsigned)blocks, 256>>>(conf, loc, priors, tboxes, tlabels,
                                            B, P, C, T);
    }
    // 5. per-batch hard-negative top-k sum
    k_select<<<B, SEL_THREADS>>>(P);
    // 6. finalize
    k_final<<<1, NSTRIPE>>>(out, B);
}

// round 11
// speedup vs baseline: 1.6462x; 1.1612x over previous
#include <cuda_runtime.h>
#include <math.h>
#include <stdint.h>

// Problem-size maxima (fixed benchmark shape B=64, P=24564, C=81, T=50)
#define BMAX 64
#define PMAX 24564
#define TMAX 50
#define NSTRIPE 512

// ---------------- scratch (__device__ globals; no allocation allowed) -------
__device__ float               g_bt_ov [BMAX * PMAX];   // best truth overlap per prior
__device__ int                 g_bt_idx[BMAX * PMAX];   // best truth index per prior
__device__ float               g_mine  [BMAX * PMAX];   // loss_mine = pos ? 0 : ce
__device__ float               g_lse   [BMAX * PMAX];   // logsumexp per row
__device__ unsigned long long  g_best_enc[BMAX * TMAX]; // per-gt best prior (encoded)
__device__ int                 g_num_pos[BMAX];
__device__ double              g_lossl_part[NSTRIPE];   // striped accumulators
__device__ double              g_lossc_part[NSTRIPE];

// ---------------- init ------------------------------------------------------
__global__ void k_init(int B, int T) {
    int i = blockIdx.x * blockDim.x + threadIdx.x;
    if (i < NSTRIPE) { g_lossl_part[i] = 0.0; g_lossc_part[i] = 0.0; }
    if (i < B) g_num_pos[i] = 0;
    if (i < B * T) g_best_enc[i] = 0ull;
}

// ---------------- matching: per-prior best-truth + per-gt best-prior --------
__global__ void k_match(const float* __restrict__ priors,
                        const float* __restrict__ tboxes,
                        int P, int T) {
    int b = blockIdx.y;
    __shared__ float4 s_t[TMAX];
    __shared__ float  s_ar[TMAX];
    __shared__ unsigned long long s_best[TMAX];
    int tid = threadIdx.x;
    if (tid < T) {
        const float* tb = tboxes + ((size_t)b * T + tid) * 4;
        float x1 = tb[0], y1 = tb[1], x2 = tb[2], y2 = tb[3];
        s_t[tid] = make_float4(x1, y1, x2, y2);
        s_ar[tid] = (x2 - x1) * (y2 - y1);
        s_best[tid] = 0ull;
    }
    __syncthreads();

    int p = blockIdx.x * blockDim.x + tid;
    bool valid = (p < P);
    float px1, py1, px2, py2, areaB;
    if (valid) {
        float4 pr = ((const float4*)priors)[p];
        px1 = pr.x - pr.z * 0.5f; py1 = pr.y - pr.w * 0.5f;
        px2 = pr.x + pr.z * 0.5f; py2 = pr.y + pr.w * 0.5f;
        areaB = (px2 - px1) * (py2 - py1);
    } else {
        px1 = 3e9f; py1 = 3e9f; px2 = 3e9f; py2 = 3e9f; areaB = 0.f;
    }

    float best = -1.0f; int bestt = 0;
    int lane = tid & 31;
    for (int t = 0; t < T; t++) {
        float4 g = s_t[t];
        float ix = fminf(g.z, px2) - fmaxf(g.x, px1);
        float iy = fminf(g.w, py2) - fmaxf(g.y, py1);
        float inter = fmaxf(ix, 0.f) * fmaxf(iy, 0.f);
        float ov = inter / (s_ar[t] + areaB - inter);   // exact div (matches ref ties)
        if (ov > best) { best = ov; bestt = t; }        // strict > : first-t ties
        unsigned bits = valid ? __float_as_uint(ov) : 0u;
        unsigned wmax = __reduce_max_sync(0xFFFFFFFFu, bits);
        unsigned bal  = __ballot_sync(0xFFFFFFFFu, bits == wmax);
        if (lane == (__ffs(bal) - 1)) {
            unsigned long long enc = (((unsigned long long)wmax) << 32) |
                                     (unsigned long long)(0xFFFFFFFFu - (unsigned)p);
            if (enc > s_best[t]) atomicMax(&s_best[t], enc);
        }
    }
    if (valid) {
        g_bt_ov [(size_t)b * P + p] = best;
        g_bt_idx[(size_t)b * P + p] = bestt;
    }
    __syncthreads();
    if (tid < T && s_best[tid]) atomicMax(&g_best_enc[b * T + tid], s_best[tid]);
}

// ---------------- force-match best prior of each gt -------------------------
__global__ void k_force(int B, int P, int T) {
    int b = blockIdx.x * blockDim.x + threadIdx.x;
    if (b >= B) return;
    for (int t = 0; t < T; t++) {
        unsigned long long enc = g_best_enc[b * T + t];
        unsigned p = enc ? (0xFFFFFFFFu - (unsigned)(enc & 0xFFFFFFFFull)) : 0u;
        g_bt_ov [(size_t)b * P + p] = 2.0f;
        g_bt_idx[(size_t)b * P + p] = t;
    }
}

// ---------------- shared epilogue helpers -----------------------------------
__device__ __forceinline__ float sl1(float d) {
    float a = fabsf(d);
    return (a < 1.0f) ? 0.5f * d * d : a - 0.5f;
}

__device__ __forceinline__ void pos_epilogue(int bp, int b, int p, int T, int ti, float ce,
                                             const float* __restrict__ loc,
                                             const float* __restrict__ priors,
                                             const float* __restrict__ tboxes) {
    atomicAdd(&g_num_pos[b], 1);
    atomicAdd(&g_lossc_part[bp & (NSTRIPE - 1)], (double)ce);
    float4 ld = ((const float4*)loc)[bp];
    float4 pr = ((const float4*)priors)[p];
    const float* tb = tboxes + ((size_t)b * T + ti) * 4;
    float gx = ((tb[0] + tb[2]) * 0.5f - pr.x) / (0.1f * pr.z);
    float gy = ((tb[1] + tb[3]) * 0.5f - pr.y) / (0.1f * pr.w);
    float gw = logf((tb[2] - tb[0]) / pr.z) / 0.2f;
    float gh = logf((tb[3] - tb[1]) / pr.w) / 0.2f;
    float ll = sl1(ld.x - gx) + sl1(ld.y - gy) + sl1(ld.z - gw) + sl1(ld.w - gh);
    atomicAdd(&g_lossl_part[bp & (NSTRIPE - 1)], (double)ll);
}

// ---------------- streaming logsumexp: C==81, 8 lanes/row, 4 rows/warp ------
// lane l of group g sums elements l, l+8, ..., l+72 (and l==0 adds elem 80) of
// row warp*4+g. No per-element row predication; 3-level shuffle reduces all 4
// rows at once; one LG2 slot per warp.
__global__ void k_lse81(const float* __restrict__ conf, int BP) {
    int warp = (int)((blockIdx.x * (size_t)blockDim.x + threadIdx.x) >> 5);
    int lane = threadIdx.x & 31;
    int l = lane & 7;
    int row = warp * 4 + (lane >> 3);
    if (row >= BP) return;

    const float* base = conf + (size_t)row * 81 + l;
    float s = 0.f;
    #pragma unroll
    for (int k = 0; k < 10; k++) s += __expf(base[8 * k]);
    if (l == 0) s += __expf(base[80]);

    s += __shfl_xor_sync(0xFFFFFFFFu, s, 4);
    s += __shfl_xor_sync(0xFFFFFFFFu, s, 2);
    s += __shfl_xor_sync(0xFFFFFFFFu, s, 1);
    float lse = __logf(s);
    if (l == 0) g_lse[row] = lse;
}

// ---------------- per-row epilogue: mine + positives ------------------------
__global__ void k_post(const float* __restrict__ conf,
                       const float* __restrict__ loc,
                       const float* __restrict__ priors,
                       const float* __restrict__ tboxes,
                       const int*   __restrict__ tlabels,
                       int P, int C, int T) {
    int b = blockIdx.y;
    int p = blockIdx.x * blockDim.x + threadIdx.x;
    if (p >= P) return;
    int bp = b * P + p;

    float ov  = g_bt_ov[bp];
    int   ti  = g_bt_idx[bp];
    float lse = g_lse[bp];
    int lab = tlabels[b * T + ti];
    int ct  = (ov < 0.5f) ? 0 : (lab + 1);
    float tgt = conf[(size_t)bp * C + ct];
    float ce = lse - tgt;
    bool pos = (ct > 0);
    g_mine[bp] = pos ? 0.f : ce;
    if (pos) pos_epilogue(bp, b, p, T, ti, ce, loc, priors, tboxes);
}

// ---------------- generic fallback ce (any C) -------------------------------
__global__ void k_ce_gen(const float* __restrict__ conf,
                         const float* __restrict__ loc,
                         const float* __restrict__ priors,
                         const float* __restrict__ tboxes,
                         const int*   __restrict__ tlabels,
                         int B, int P, int C, int T) {
    int wg = (int)((blockIdx.x * (size_t)blockDim.x + threadIdx.x) >> 5);
    int lane = threadIdx.x & 31;
    if (wg >= B * P) return;
    int b = wg / P, p = wg % P;
    size_t base = ((size_t)b * P + p) * (size_t)C;

    float m = -INFINITY;
    for (int c = lane; c < C; c += 32) m = fmaxf(m, conf[base + c]);
    #pragma unroll
    for (int o = 16; o > 0; o >>= 1) m = fmaxf(m, __shfl_xor_sync(0xFFFFFFFFu, m, o));
    float s = 0.f;
    for (int c = lane; c < C; c += 32) s += __expf(conf[base + c] - m);
    #pragma unroll
    for (int o = 16; o > 0; o >>= 1) s += __shfl_xor_sync(0xFFFFFFFFu, s, o);
    float lse = m + __logf(s);

    if (lane == 0) {
        int bp = b * P + p;
        float ov = g_bt_ov[bp];
        int   ti = g_bt_idx[bp];
        int conf_t = (ov < 0.5f) ? 0 : (tlabels[b * T + ti] + 1);
        float ce = lse - conf[base + conf_t];
        bool pos = (conf_t > 0);
        g_mine[bp] = pos ? 0.0f : ce;
        if (pos) pos_epilogue(bp, b, p, T, ti, ce, loc, priors, tboxes);
    }
}

// ---------------- per-batch top-k sum via 8-bit MSB radix select ------------
#define SEL_THREADS 512
__global__ void k_select(int P) {
    int b = blockIdx.x;
    __shared__ unsigned s_cnt[256];
    __shared__ unsigned s_prefix;
    __shared__ int s_k;
    __shared__ double s_sum[SEL_THREADS];
    int tid = threadIdx.x;
    int lane = tid & 31;

    if (tid == 0) {
        int np = g_num_pos[b];
        int k = 3 * np;
        if (k > P - 1) k = P - 1;
        s_k = k;
        s_prefix = 0u;
    }
    __syncthreads();
    if (s_k <= 0) return;

    const float*  mine  = g_mine + (size_t)b * P;
    const float4* mine4 = (const float4*)mine;
    int P4 = P >> 2;
    int tail = P & 3;
    int iters = (P4 + SEL_THREADS - 1) / SEL_THREADS;

    for (int shift = 24; shift >= 0; shift -= 8) {
        if (tid < 256) s_cnt[tid] = 0;
        __syncthreads();
        unsigned pref = s_prefix;
        unsigned hm = (shift == 24) ? 0u : (0xFFFFFFFFu << (shift + 8));
        for (int it = 0; it < iters; it++) {
            int i = it * SEL_THREADS + tid;
            float4 v = make_float4(0.f, 0.f, 0.f, 0.f);
            bool valid = (i < P4);
            if (valid) v = mine4[i];
            unsigned u[4] = {__float_as_uint(v.x), __float_as_uint(v.y),
                             __float_as_uint(v.z), __float_as_uint(v.w)};
            #pragma unroll
            for (int j = 0; j < 4; j++) {
                bool ok = valid && ((u[j] & hm) == (pref & hm));
                unsigned bin = ok ? ((u[j] >> shift) & 255u) : 0xFFFFFFFFu;
                unsigned mm = __match_any_sync(0xFFFFFFFFu, bin);
                if (ok && lane == (__ffs(mm) - 1))
                    atomicAdd(&s_cnt[bin], (unsigned)__popc(mm));
            }
        }
        if (tid < tail) {
            unsigned v = __float_as_uint(mine[P4 * 4 + tid]);
            if ((v & hm) == (pref & hm))
                atomicAdd(&s_cnt[(v >> shift) & 255u], 1u);
        }
        __syncthreads();
        if (tid == 0) {
            int k = s_k;
            int cum = 0;
            unsigned g = 0;
            for (int d = 255; d >= 0; d--) {
                int c = (int)s_cnt[d];
                if (cum + c >= k) { g = (unsigned)d; s_k = k - cum; break; }
                cum += c;
            }
            s_prefix = pref | (g << shift);
        }
        __syncthreads();
    }

    unsigned thr = s_prefix;
    double sum = 0.0;
    for (int i = tid; i < P4; i += SEL_THREADS) {
        float4 v = mine4[i];
        if (__float_as_uint(v.x) > thr) sum += (double)v.x;
        if (__float_as_uint(v.y) > thr) sum += (double)v.y;
        if (__float_as_uint(v.z) > thr) sum += (double)v.z;
        if (__float_as_uint(v.w) > thr) sum += (double)v.w;
    }
    if (tid < tail) {
        float f = mine[P4 * 4 + tid];
        if (__float_as_uint(f) > thr) sum += (double)f;
    }
    if (tid == 0) sum += (double)s_k * (double)__uint_as_float(thr);
    s_sum[tid] = sum;
    __syncthreads();
    #pragma unroll
    for (int o = SEL_THREADS / 2; o > 0; o >>= 1) {
        if (tid < o) s_sum[tid] += s_sum[tid + o];
        __syncthreads();
    }
    if (tid == 0) atomicAdd(&g_lossc_part[b & (NSTRIPE - 1)], s_sum[0]);
}

// ---------------- finalize (parallel reduce of striped partials) ------------
__global__ void k_final(float* out, int B) {
    __shared__ double s_l[NSTRIPE];
    __shared__ double s_c[NSTRIPE];
    __shared__ int    s_n[64];
    int tid = threadIdx.x;
    s_l[tid] = g_lossl_part[tid];
    s_c[tid] = g_lossc_part[tid];
    s_n[tid & 63] = 0;
    __syncthreads();
    if (tid < B) s_n[tid] = g_num_pos[tid];
    __syncthreads();
    #pragma unroll
    for (int o = NSTRIPE / 2; o > 0; o >>= 1) {
        if (tid < o) { s_l[tid] += s_l[tid + o]; s_c[tid] += s_c[tid + o]; }
        if (o <= 32 && tid < o) s_n[tid] += s_n[tid + o];
        __syncthreads();
    }
    if (tid == 0) {
        int n = s_n[0];
        double nn = (n < 1) ? 1.0 : (double)n;
        out[0] = (float)(s_l[0] / nn);
        out[1] = (float)(s_c[0] / nn);
    }
}

// ---------------- launch ----------------------------------------------------
extern "C" void kernel_launch(void* const* d_in, const int* in_sizes, int n_in,
                              void* d_out, int out_size) {
    const float* loc     = (const float*)d_in[0];
    const float* conf    = (const float*)d_in[1];
    const float* priors  = (const float*)d_in[2];
    const float* tboxes  = (const float*)d_in[3];
    const int*   tlabels = (const int*)  d_in[4];
    float* out = (float*)d_out;

    int P  = in_sizes[2] / 4;
    int B  = in_sizes[0] / (4 * P);
    int T  = in_sizes[4] / B;
    int C  = (int)((long long)in_sizes[1] / ((long long)B * P));
    int BP = B * P;

    // 1. init scratch accumulators
    {
        int n = B * T;
        if (n < NSTRIPE) n = NSTRIPE;
        k_init<<<(n + 255) / 256, 256>>>(B, T);
    }
    // 2. streaming logsumexp (independent of matching; longest kernel first)
    bool fast = (C == 81);
    if (fast) {
        long long warps = ((long long)BP + 3) / 4;
        long long blocks = (warps + 7) / 8;            // 8 warps / block
        k_lse81<<<(unsigned)blocks, 256>>>(conf, BP);
    }
    // 3. matching
    {
        dim3 grid((P + 255) / 256, B);
        k_match<<<grid, 256>>>(priors, tboxes, P, T);
    }
    // 4. force-match best prior per gt
    k_force<<<(B + 63) / 64, 64>>>(B, P, T);
    // 5. ce epilogue
    if (fast) {
        dim3 grid((P + 255) / 256, B);
        k_post<<<grid, 256>>>(conf, loc, priors, tboxes, tlabels, P, C, T);
    } else {
        long long total_warps = (long long)BP;
        long long blocks = (total_warps + 7) / 8;
        k_ce_gen<<<(unsigned)blocks, 256>>>(conf, loc, priors, tboxes, tlabels,
                                            B, P, C, T);
    }
    // 6. per-batch hard-negative top-k sum
    k_select<<<B, SEL_THREADS>>>(P);
    // 7. finalize
    k_final<<<1, NSTRIPE>>>(out, B);
}

// round 12
// speedup vs baseline: 1.7177x; 1.0434x over previous
#include <cuda_runtime.h>
#include <math.h>
#include <stdint.h>

// Problem-size maxima (fixed benchmark shape B=64, P=24564, C=81, T=50)
#define BMAX 64
#define PMAX 24564
#define TMAX 50
#define NSTRIPE 512

// ---------------- scratch (__device__ globals; no allocation allowed) -------
__device__ float               g_bt_ov [BMAX * PMAX];   // best truth overlap per prior
__device__ int                 g_bt_idx[BMAX * PMAX];   // best truth index per prior
__device__ float               g_mine  [BMAX * PMAX];   // loss_mine = pos ? 0 : ce
__device__ float               g_lse   [BMAX * PMAX];   // logsumexp per row
__device__ unsigned long long  g_best_enc[BMAX * TMAX]; // per-gt best prior (encoded)
__device__ int                 g_num_pos[BMAX];
__device__ double              g_lossl_part[NSTRIPE];   // striped accumulators
__device__ double              g_lossc_part[NSTRIPE];

// ---------------- init ------------------------------------------------------
__global__ void k_init(int B, int T) {
    int i = blockIdx.x * blockDim.x + threadIdx.x;
    if (i < NSTRIPE) { g_lossl_part[i] = 0.0; g_lossc_part[i] = 0.0; }
    if (i < B) g_num_pos[i] = 0;
    if (i < B * T) g_best_enc[i] = 0ull;
}

// ---------------- fused matching + streaming logsumexp ----------------------
// Blocks [0, matchBlocks) run the IoU matching (ALU/issue-bound).
// Blocks [matchBlocks, ...) run the conf logsumexp (DRAM-bound).
// The two use disjoint resources, so co-residency overlaps them for free.

__device__ __forceinline__ void match_body(const float* __restrict__ priors,
                                           const float* __restrict__ tboxes,
                                           int P, int T, int b, int pblk) {
    __shared__ float4 s_t[TMAX];
    __shared__ float  s_ar[TMAX];
    __shared__ unsigned long long s_best[TMAX];
    int tid = threadIdx.x;
    if (tid < T) {
        const float* tb = tboxes + ((size_t)b * T + tid) * 4;
        float x1 = tb[0], y1 = tb[1], x2 = tb[2], y2 = tb[3];
        s_t[tid] = make_float4(x1, y1, x2, y2);
        s_ar[tid] = (x2 - x1) * (y2 - y1);
        s_best[tid] = 0ull;
    }
    __syncthreads();

    int p = pblk * 256 + tid;
    bool valid = (p < P);
    float px1, py1, px2, py2, areaB;
    if (valid) {
        float4 pr = ((const float4*)priors)[p];
        px1 = pr.x - pr.z * 0.5f; py1 = pr.y - pr.w * 0.5f;
        px2 = pr.x + pr.z * 0.5f; py2 = pr.y + pr.w * 0.5f;
        areaB = (px2 - px1) * (py2 - py1);
    } else {
        px1 = 3e9f; py1 = 3e9f; px2 = 3e9f; py2 = 3e9f; areaB = 0.f;
    }

    float best = -1.0f; int bestt = 0;
    int lane = tid & 31;
    for (int t = 0; t < T; t++) {
        float4 g = s_t[t];
        float ix = fminf(g.z, px2) - fmaxf(g.x, px1);
        float iy = fminf(g.w, py2) - fmaxf(g.y, py1);
        float inter = fmaxf(ix, 0.f) * fmaxf(iy, 0.f);
        float ov = inter / (s_ar[t] + areaB - inter);   // exact div (matches ref ties)
        if (ov > best) { best = ov; bestt = t; }        // strict > : first-t ties
        unsigned bits = valid ? __float_as_uint(ov) : 0u;
        unsigned wmax = __reduce_max_sync(0xFFFFFFFFu, bits);
        unsigned bal  = __ballot_sync(0xFFFFFFFFu, bits == wmax);
        if (lane == (__ffs(bal) - 1)) {
            unsigned long long enc = (((unsigned long long)wmax) << 32) |
                                     (unsigned long long)(0xFFFFFFFFu - (unsigned)p);
            if (enc > s_best[t]) atomicMax(&s_best[t], enc);
        }
    }
    if (valid) {
        g_bt_ov [(size_t)b * P + p] = best;
        g_bt_idx[(size_t)b * P + p] = bestt;
    }
    __syncthreads();
    if (tid < T && s_best[tid]) atomicMax(&g_best_enc[b * T + tid], s_best[tid]);
}

__device__ __forceinline__ void lse_body(const float* __restrict__ conf,
                                         int BP, int lseBlk) {
    int warp = lseBlk * 8 + (threadIdx.x >> 5);
    int lane = threadIdx.x & 31;
    int l = lane & 7;
    int row = warp * 4 + (lane >> 3);
    if (row >= BP) return;

    const float* base = conf + (size_t)row * 81 + l;
    float s = 0.f;
    #pragma unroll
    for (int k = 0; k < 10; k++) s += __expf(base[8 * k]);
    if (l == 0) s += __expf(base[80]);

    s += __shfl_xor_sync(0xFFFFFFFFu, s, 4);
    s += __shfl_xor_sync(0xFFFFFFFFu, s, 2);
    s += __shfl_xor_sync(0xFFFFFFFFu, s, 1);
    float lse = __logf(s);
    if (l == 0) g_lse[row] = lse;
}

__global__ void k_fused(const float* __restrict__ priors,
                        const float* __restrict__ tboxes,
                        const float* __restrict__ conf,
                        int P, int T, int BP, int matchBlocks, int mbx) {
    if ((int)blockIdx.x < matchBlocks) {
        int mb = blockIdx.x;
        match_body(priors, tboxes, P, T, mb / mbx, mb % mbx);
    } else {
        lse_body(conf, BP, blockIdx.x - matchBlocks);
    }
}

// ---------------- force-match best prior of each gt -------------------------
// Prefetch all enc values (independent loads, MLP-overlapped), then store.
__global__ void k_force(int B, int P, int T) {
    int b = blockIdx.x * blockDim.x + threadIdx.x;
    if (b >= B) return;
    unsigned long long e[TMAX];
    #pragma unroll
    for (int t = 0; t < TMAX; t++)
        if (t < T) e[t] = g_best_enc[b * T + t];
    #pragma unroll
    for (int t = 0; t < TMAX; t++) {
        if (t < T) {
            unsigned p = e[t] ? (0xFFFFFFFFu - (unsigned)(e[t] & 0xFFFFFFFFull)) : 0u;
            g_bt_ov [(size_t)b * P + p] = 2.0f;
            g_bt_idx[(size_t)b * P + p] = t;
        }
    }
}

// ---------------- shared epilogue helpers -----------------------------------
__device__ __forceinline__ float sl1(float d) {
    float a = fabsf(d);
    return (a < 1.0f) ? 0.5f * d * d : a - 0.5f;
}

__device__ __forceinline__ void pos_epilogue(int bp, int b, int p, int T, int ti, float ce,
                                             const float* __restrict__ loc,
                                             const float* __restrict__ priors,
                                             const float* __restrict__ tboxes) {
    atomicAdd(&g_num_pos[b], 1);
    atomicAdd(&g_lossc_part[bp & (NSTRIPE - 1)], (double)ce);
    float4 ld = ((const float4*)loc)[bp];
    float4 pr = ((const float4*)priors)[p];
    const float* tb = tboxes + ((size_t)b * T + ti) * 4;
    float gx = ((tb[0] + tb[2]) * 0.5f - pr.x) / (0.1f * pr.z);
    float gy = ((tb[1] + tb[3]) * 0.5f - pr.y) / (0.1f * pr.w);
    float gw = logf((tb[2] - tb[0]) / pr.z) / 0.2f;
    float gh = logf((tb[3] - tb[1]) / pr.w) / 0.2f;
    float ll = sl1(ld.x - gx) + sl1(ld.y - gy) + sl1(ld.z - gw) + sl1(ld.w - gh);
    atomicAdd(&g_lossl_part[bp & (NSTRIPE - 1)], (double)ll);
}

// ---------------- per-row epilogue: mine + positives ------------------------
__global__ void k_post(const float* __restrict__ conf,
                       const float* __restrict__ loc,
                       const float* __restrict__ priors,
                       const float* __restrict__ tboxes,
                       const int*   __restrict__ tlabels,
                       int P, int C, int T) {
    int b = blockIdx.y;
    int p = blockIdx.x * blockDim.x + threadIdx.x;
    if (p >= P) return;
    int bp = b * P + p;

    float ov  = g_bt_ov[bp];
    int   ti  = g_bt_idx[bp];
    float lse = g_lse[bp];
    int lab = tlabels[b * T + ti];
    int ct  = (ov < 0.5f) ? 0 : (lab + 1);
    float tgt = conf[(size_t)bp * C + ct];
    float ce = lse - tgt;
    bool pos = (ct > 0);
    g_mine[bp] = pos ? 0.f : ce;
    if (pos) pos_epilogue(bp, b, p, T, ti, ce, loc, priors, tboxes);
}

// ---------------- generic fallback ce (any C) -------------------------------
__global__ void k_ce_gen(const float* __restrict__ conf,
                         const float* __restrict__ loc,
                         const float* __restrict__ priors,
                         const float* __restrict__ tboxes,
                         const int*   __restrict__ tlabels,
                         int B, int P, int C, int T) {
    int wg = (int)((blockIdx.x * (size_t)blockDim.x + threadIdx.x) >> 5);
    int lane = threadIdx.x & 31;
    if (wg >= B * P) return;
    int b = wg / P, p = wg % P;
    size_t base = ((size_t)b * P + p) * (size_t)C;

    float m = -INFINITY;
    for (int c = lane; c < C; c += 32) m = fmaxf(m, conf[base + c]);
    #pragma unroll
    for (int o = 16; o > 0; o >>= 1) m = fmaxf(m, __shfl_xor_sync(0xFFFFFFFFu, m, o));
    float s = 0.f;
    for (int c = lane; c < C; c += 32) s += __expf(conf[base + c] - m);
    #pragma unroll
    for (int o = 16; o > 0; o >>= 1) s += __shfl_xor_sync(0xFFFFFFFFu, s, o);
    float lse = m + __logf(s);

    if (lane == 0) {
        int bp = b * P + p;
        float ov = g_bt_ov[bp];
        int   ti = g_bt_idx[bp];
        int conf_t = (ov < 0.5f) ? 0 : (tlabels[b * T + ti] + 1);
        float ce = lse - conf[base + conf_t];
        bool pos = (conf_t > 0);
        g_mine[bp] = pos ? 0.0f : ce;
        if (pos) pos_epilogue(bp, b, p, T, ti, ce, loc, priors, tboxes);
    }
}

// ---------------- per-batch top-k sum via 8-bit MSB radix select ------------
#define SEL_THREADS 512
__global__ void k_select(int P) {
    int b = blockIdx.x;
    __shared__ unsigned s_cnt[256];
    __shared__ unsigned s_prefix;
    __shared__ int s_k;
    __shared__ double s_sum[SEL_THREADS];
    int tid = threadIdx.x;
    int lane = tid & 31;

    if (tid == 0) {
        int np = g_num_pos[b];
        int k = 3 * np;
        if (k > P - 1) k = P - 1;
        s_k = k;
        s_prefix = 0u;
    }
    __syncthreads();
    if (s_k <= 0) return;

    const float*  mine  = g_mine + (size_t)b * P;
    const float4* mine4 = (const float4*)mine;
    int P4 = P >> 2;
    int tail = P & 3;
    int iters = (P4 + SEL_THREADS - 1) / SEL_THREADS;

    for (int shift = 24; shift >= 0; shift -= 8) {
        if (tid < 256) s_cnt[tid] = 0;
        __syncthreads();
        unsigned pref = s_prefix;
        unsigned hm = (shift == 24) ? 0u : (0xFFFFFFFFu << (shift + 8));
        for (int it = 0; it < iters; it++) {
            int i = it * SEL_THREADS + tid;
            float4 v = make_float4(0.f, 0.f, 0.f, 0.f);
            bool valid = (i < P4);
            if (valid) v = mine4[i];
            unsigned u[4] = {__float_as_uint(v.x), __float_as_uint(v.y),
                             __float_as_uint(v.z), __float_as_uint(v.w)};
            #pragma unroll
            for (int j = 0; j < 4; j++) {
                bool ok = valid && ((u[j] & hm) == (pref & hm));
                unsigned bin = ok ? ((u[j] >> shift) & 255u) : 0xFFFFFFFFu;
                unsigned mm = __match_any_sync(0xFFFFFFFFu, bin);
                if (ok && lane == (__ffs(mm) - 1))
                    atomicAdd(&s_cnt[bin], (unsigned)__popc(mm));
            }
        }
        if (tid < tail) {
            unsigned v = __float_as_uint(mine[P4 * 4 + tid]);
            if ((v & hm) == (pref & hm))
                atomicAdd(&s_cnt[(v >> shift) & 255u], 1u);
        }
        __syncthreads();
        if (tid == 0) {
            int k = s_k;
            int cum = 0;
            unsigned g = 0;
            for (int d = 255; d >= 0; d--) {
                int c = (int)s_cnt[d];
                if (cum + c >= k) { g = (unsigned)d; s_k = k - cum; break; }
                cum += c;
            }
            s_prefix = pref | (g << shift);
        }
        __syncthreads();
    }

    unsigned thr = s_prefix;
    double sum = 0.0;
    for (int i = tid; i < P4; i += SEL_THREADS) {
        float4 v = mine4[i];
        if (__float_as_uint(v.x) > thr) sum += (double)v.x;
        if (__float_as_uint(v.y) > thr) sum += (double)v.y;
        if (__float_as_uint(v.z) > thr) sum += (double)v.z;
        if (__float_as_uint(v.w) > thr) sum += (double)v.w;
    }
    if (tid < tail) {
        float f = mine[P4 * 4 + tid];
        if (__float_as_uint(f) > thr) sum += (double)f;
    }
    if (tid == 0) sum += (double)s_k * (double)__uint_as_float(thr);
    s_sum[tid] = sum;
    __syncthreads();
    #pragma unroll
    for (int o = SEL_THREADS / 2; o > 0; o >>= 1) {
        if (tid < o) s_sum[tid] += s_sum[tid + o];
        __syncthreads();
    }
    if (tid == 0) atomicAdd(&g_lossc_part[b & (NSTRIPE - 1)], s_sum[0]);
}

// ---------------- finalize (parallel reduce of striped partials) ------------
__global__ void k_final(float* out, int B) {
    __shared__ double s_l[NSTRIPE];
    __shared__ double s_c[NSTRIPE];
    __shared__ int    s_n[64];
    int tid = threadIdx.x;
    s_l[tid] = g_lossl_part[tid];
    s_c[tid] = g_lossc_part[tid];
    s_n[tid & 63] = 0;
    __syncthreads();
    if (tid < B) s_n[tid] = g_num_pos[tid];
    __syncthreads();
    #pragma unroll
    for (int o = NSTRIPE / 2; o > 0; o >>= 1) {
        if (tid < o) { s_l[tid] += s_l[tid + o]; s_c[tid] += s_c[tid + o]; }
        if (o <= 32 && tid < o) s_n[tid] += s_n[tid + o];
        __syncthreads();
    }
    if (tid == 0) {
        int n = s_n[0];
        double nn = (n < 1) ? 1.0 : (double)n;
        out[0] = (float)(s_l[0] / nn);
        out[1] = (float)(s_c[0] / nn);
    }
}

// ---------------- launch ----------------------------------------------------
extern "C" void kernel_launch(void* const* d_in, const int* in_sizes, int n_in,
                              void* d_out, int out_size) {
    const float* loc     = (const float*)d_in[0];
    const float* conf    = (const float*)d_in[1];
    const float* priors  = (const float*)d_in[2];
    const float* tboxes  = (const float*)d_in[3];
    const int*   tlabels = (const int*)  d_in[4];
    float* out = (float*)d_out;

    int P  = in_sizes[2] / 4;
    int B  = in_sizes[0] / (4 * P);
    int T  = in_sizes[4] / B;
    int C  = (int)((long long)in_sizes[1] / ((long long)B * P));
    int BP = B * P;

    // 1. init scratch accumulators
    {
        int n = B * T;
        if (n < NSTRIPE) n = NSTRIPE;
        k_init<<<(n + 255) / 256, 256>>>(B, T);
    }
    bool fast = (C == 81);
    int mbx = (P + 255) / 256;
    int matchBlocks = mbx * B;
    if (fast) {
        // 2. fused matching + logsumexp (independent work, co-resident overlap)
        long long warps = ((long long)BP + 3) / 4;
        long long lseBlocks = (warps + 7) / 8;         // 8 warps / block
        k_fused<<<(unsigned)(matchBlocks + lseBlocks), 256>>>(
            priors, tboxes, conf, P, T, BP, matchBlocks, mbx);
    } else {
        dim3 grid(mbx, B);
        k_fused<<<dim3(matchBlocks), 256>>>(priors, tboxes, conf, P, T, BP,
                                            matchBlocks, mbx);
    }
    // 3. force-match best prior per gt (prefetched loads)
    k_force<<<(B + 63) / 64, 64>>>(B, P, T);
    // 4. ce epilogue
    if (fast) {
        dim3 grid(mbx, B);
        k_post<<<grid, 256>>>(conf, loc, priors, tboxes, tlabels, P, C, T);
    } else {
        long long total_warps = (long long)BP;
        long long blocks = (total_warps + 7) / 8;
        k_ce_gen<<<(unsigned)blocks, 256>>>(conf, loc, priors, tboxes, tlabels,
                                            B, P, C, T);
    }
    // 5. per-batch hard-negative top-k sum
    k_select<<<B, SEL_THREADS>>>(P);
    // 6. finalize
    k_final<<<1, NSTRIPE>>>(out, B);
}

// round 13
// speedup vs baseline: 2.2260x; 1.2959x over previous
#include <cuda_runtime.h>
#include <math.h>
#include <stdint.h>

// Problem-size maxima (fixed benchmark shape B=64, P=24564, C=81, T=50)
#define BMAX 64
#define PMAX 24564
#define TMAX 50
#define NSTRIPE 512

// ---------------- scratch (__device__ globals; no allocation allowed) -------
__device__ float               g_bt_ov [BMAX * PMAX];   // best truth overlap per prior
__device__ int                 g_bt_idx[BMAX * PMAX];   // best truth index per prior
__device__ float               g_mine  [BMAX * PMAX];   // loss_mine = pos ? 0 : ce
__device__ float               g_lse   [BMAX * PMAX];   // logsumexp per row
__device__ float               g_bg    [BMAX * PMAX];   // background logit conf[row][0]
__device__ unsigned long long  g_best_enc[BMAX * TMAX]; // per-gt best prior (encoded)
__device__ int                 g_num_pos[BMAX];
__device__ double              g_lossl_part[NSTRIPE];   // striped accumulators
__device__ double              g_lossc_part[NSTRIPE];

// ---------------- init ------------------------------------------------------
__global__ void k_init(int B, int T) {
    int i = blockIdx.x * blockDim.x + threadIdx.x;
    if (i < NSTRIPE) { g_lossl_part[i] = 0.0; g_lossc_part[i] = 0.0; }
    if (i < B) g_num_pos[i] = 0;
    if (i < B * T) g_best_enc[i] = 0ull;
}

// ---------------- fused matching + streaming logsumexp ----------------------
// Blocks [0, matchBlocks) run the IoU matching (ALU/issue-bound).
// Blocks [matchBlocks, ...) run the conf logsumexp (DRAM-bound).
// Disjoint resources -> co-residency overlaps them for free.

__device__ __forceinline__ void match_body(const float* __restrict__ priors,
                                           const float* __restrict__ tboxes,
                                           int P, int T, int b, int pblk) {
    __shared__ float4 s_t[TMAX];
    __shared__ float  s_ar[TMAX];
    __shared__ unsigned long long s_best[TMAX];
    int tid = threadIdx.x;
    if (tid < T) {
        const float* tb = tboxes + ((size_t)b * T + tid) * 4;
        float x1 = tb[0], y1 = tb[1], x2 = tb[2], y2 = tb[3];
        s_t[tid] = make_float4(x1, y1, x2, y2);
        s_ar[tid] = (x2 - x1) * (y2 - y1);
        s_best[tid] = 0ull;
    }
    __syncthreads();

    int p = pblk * 256 + tid;
    bool valid = (p < P);
    float px1, py1, px2, py2, areaB;
    if (valid) {
        float4 pr = ((const float4*)priors)[p];
        px1 = pr.x - pr.z * 0.5f; py1 = pr.y - pr.w * 0.5f;
        px2 = pr.x + pr.z * 0.5f; py2 = pr.y + pr.w * 0.5f;
        areaB = (px2 - px1) * (py2 - py1);
    } else {
        px1 = 3e9f; py1 = 3e9f; px2 = 3e9f; py2 = 3e9f; areaB = 0.f;
    }

    float best = -1.0f; int bestt = 0;
    int lane = tid & 31;
    for (int t = 0; t < T; t++) {
        float4 g = s_t[t];
        float ix = fminf(g.z, px2) - fmaxf(g.x, px1);
        float iy = fminf(g.w, py2) - fmaxf(g.y, py1);
        float inter = fmaxf(ix, 0.f) * fmaxf(iy, 0.f);
        float ov = __fdividef(inter, s_ar[t] + areaB - inter);
        if (ov > best) { best = ov; bestt = t; }        // strict > : first-t ties
        unsigned bits = valid ? __float_as_uint(ov) : 0u;
        unsigned wmax = __reduce_max_sync(0xFFFFFFFFu, bits);
        unsigned bal  = __ballot_sync(0xFFFFFFFFu, bits == wmax);
        if (lane == (__ffs(bal) - 1)) {
            unsigned long long enc = (((unsigned long long)wmax) << 32) |
                                     (unsigned long long)(0xFFFFFFFFu - (unsigned)p);
            if (enc > s_best[t]) atomicMax(&s_best[t], enc);
        }
    }
    if (valid) {
        g_bt_ov [(size_t)b * P + p] = best;
        g_bt_idx[(size_t)b * P + p] = bestt;
    }
    __syncthreads();
    if (tid < T && s_best[tid]) atomicMax(&g_best_enc[b * T + tid], s_best[tid]);
}

__device__ __forceinline__ void lse_body(const float* __restrict__ conf,
                                         int BP, int lseBlk) {
    int warp = lseBlk * 8 + (threadIdx.x >> 5);
    int lane = threadIdx.x & 31;
    int l = lane & 7;
    int row = warp * 4 + (lane >> 3);
    if (row >= BP) return;

    const float* base = conf + (size_t)row * 81 + l;
    float v0 = base[0];                    // lane l==0 holds the background logit
    float s = __expf(v0);
    #pragma unroll
    for (int k = 1; k < 10; k++) s += __expf(base[8 * k]);
    if (l == 0) s += __expf(base[80]);

    s += __shfl_xor_sync(0xFFFFFFFFu, s, 4);
    s += __shfl_xor_sync(0xFFFFFFFFu, s, 2);
    s += __shfl_xor_sync(0xFFFFFFFFu, s, 1);
    float lse = __logf(s);
    if (l == 0) { g_lse[row] = lse; g_bg[row] = v0; }
}

__global__ void k_fused(const float* __restrict__ priors,
                        const float* __restrict__ tboxes,
                        const float* __restrict__ conf,
                        int P, int T, int BP, int matchBlocks, int mbx) {
    if ((int)blockIdx.x < matchBlocks) {
        int mb = blockIdx.x;
        match_body(priors, tboxes, P, T, mb / mbx, mb % mbx);
    } else {
        lse_body(conf, BP, blockIdx.x - matchBlocks);
    }
}

// ---------------- force-match best prior of each gt -------------------------
__global__ void k_force(int B, int P, int T) {
    int b = blockIdx.x * blockDim.x + threadIdx.x;
    if (b >= B) return;
    unsigned long long e[TMAX];
    #pragma unroll
    for (int t = 0; t < TMAX; t++)
        if (t < T) e[t] = g_best_enc[b * T + t];
    #pragma unroll
    for (int t = 0; t < TMAX; t++) {
        if (t < T) {
            unsigned p = e[t] ? (0xFFFFFFFFu - (unsigned)(e[t] & 0xFFFFFFFFull)) : 0u;
            g_bt_ov [(size_t)b * P + p] = 2.0f;
            g_bt_idx[(size_t)b * P + p] = t;
        }
    }
}

// ---------------- shared epilogue helpers -----------------------------------
__device__ __forceinline__ float sl1(float d) {
    float a = fabsf(d);
    return (a < 1.0f) ? 0.5f * d * d : a - 0.5f;
}

__device__ __forceinline__ void pos_epilogue(int bp, int b, int p, int T, int ti, float ce,
                                             const float* __restrict__ loc,
                                             const float* __restrict__ priors,
                                             const float* __restrict__ tboxes) {
    atomicAdd(&g_num_pos[b], 1);
    atomicAdd(&g_lossc_part[bp & (NSTRIPE - 1)], (double)ce);
    float4 ld = ((const float4*)loc)[bp];
    float4 pr = ((const float4*)priors)[p];
    const float* tb = tboxes + ((size_t)b * T + ti) * 4;
    float gx = ((tb[0] + tb[2]) * 0.5f - pr.x) / (0.1f * pr.z);
    float gy = ((tb[1] + tb[3]) * 0.5f - pr.y) / (0.1f * pr.w);
    float gw = logf((tb[2] - tb[0]) / pr.z) / 0.2f;
    float gh = logf((tb[3] - tb[1]) / pr.w) / 0.2f;
    float ll = sl1(ld.x - gx) + sl1(ld.y - gy) + sl1(ld.z - gw) + sl1(ld.w - gh);
    atomicAdd(&g_lossl_part[bp & (NSTRIPE - 1)], (double)ll);
}

// ---------------- per-row epilogue: mine + positives ------------------------
// All-dense reads; the target-logit gather happens ONLY for ov>=0.5 rows (~2%).
__global__ void k_post(const float* __restrict__ conf,
                       const float* __restrict__ loc,
                       const float* __restrict__ priors,
                       const float* __restrict__ tboxes,
                       const int*   __restrict__ tlabels,
                       int P, int C, int T) {
    int b = blockIdx.y;
    int p = blockIdx.x * blockDim.x + threadIdx.x;
    if (p >= P) return;
    int bp = b * P + p;

    float ov  = g_bt_ov[bp];
    float lse = g_lse[bp];
    float bg  = g_bg[bp];

    if (ov < 0.5f) {                       // background: no gather, no label read
        g_mine[bp] = lse - bg;
        return;
    }
    int ti  = g_bt_idx[bp];
    int lab = tlabels[b * T + ti];         // tiny table, cache-resident
    int ct  = lab + 1;
    float tgt = conf[(size_t)bp * C + ct]; // rare gather
    float ce = lse - tgt;
    g_mine[bp] = 0.f;
    pos_epilogue(bp, b, p, T, ti, ce, loc, priors, tboxes);
}

// ---------------- generic fallback ce (any C) -------------------------------
__global__ void k_ce_gen(const float* __restrict__ conf,
                         const float* __restrict__ loc,
                         const float* __restrict__ priors,
                         const float* __restrict__ tboxes,
                         const int*   __restrict__ tlabels,
                         int B, int P, int C, int T) {
    int wg = (int)((blockIdx.x * (size_t)blockDim.x + threadIdx.x) >> 5);
    int lane = threadIdx.x & 31;
    if (wg >= B * P) return;
    int b = wg / P, p = wg % P;
    size_t base = ((size_t)b * P + p) * (size_t)C;

    float m = -INFINITY;
    for (int c = lane; c < C; c += 32) m = fmaxf(m, conf[base + c]);
    #pragma unroll
    for (int o = 16; o > 0; o >>= 1) m = fmaxf(m, __shfl_xor_sync(0xFFFFFFFFu, m, o));
    float s = 0.f;
    for (int c = lane; c < C; c += 32) s += __expf(conf[base + c] - m);
    #pragma unroll
    for (int o = 16; o > 0; o >>= 1) s += __shfl_xor_sync(0xFFFFFFFFu, s, o);
    float lse = m + __logf(s);

    if (lane == 0) {
        int bp = b * P + p;
        float ov = g_bt_ov[bp];
        int   ti = g_bt_idx[bp];
        int conf_t = (ov < 0.5f) ? 0 : (tlabels[b * T + ti] + 1);
        float ce = lse - conf[base + conf_t];
        bool pos = (conf_t > 0);
        g_mine[bp] = pos ? 0.0f : ce;
        if (pos) pos_epilogue(bp, b, p, T, ti, ce, loc, priors, tboxes);
    }
}

// ---------------- per-batch top-k sum via 8-bit MSB radix select ------------
#define SEL_THREADS 512
__global__ void k_select(int P) {
    int b = blockIdx.x;
    __shared__ unsigned s_cnt[256];
    __shared__ unsigned s_prefix;
    __shared__ int s_k;
    __shared__ double s_sum[SEL_THREADS];
    int tid = threadIdx.x;
    int lane = tid & 31;

    if (tid == 0) {
        int np = g_num_pos[b];
        int k = 3 * np;
        if (k > P - 1) k = P - 1;
        s_k = k;
        s_prefix = 0u;
    }
    __syncthreads();
    if (s_k <= 0) return;

    const float*  mine  = g_mine + (size_t)b * P;
    const float4* mine4 = (const float4*)mine;
    int P4 = P >> 2;
    int tail = P & 3;
    int iters = (P4 + SEL_THREADS - 1) / SEL_THREADS;

    for (int shift = 24; shift >= 0; shift -= 8) {
        if (tid < 256) s_cnt[tid] = 0;
        __syncthreads();
        unsigned pref = s_prefix;
        unsigned hm = (shift == 24) ? 0u : (0xFFFFFFFFu << (shift + 8));
        for (int it = 0; it < iters; it++) {
            int i = it * SEL_THREADS + tid;
            float4 v = make_float4(0.f, 0.f, 0.f, 0.f);
            bool valid = (i < P4);
            if (valid) v = mine4[i];
            unsigned u[4] = {__float_as_uint(v.x), __float_as_uint(v.y),
                             __float_as_uint(v.z), __float_as_uint(v.w)};
            #pragma unroll
            for (int j = 0; j < 4; j++) {
                bool ok = valid && ((u[j] & hm) == (pref & hm));
                unsigned bin = ok ? ((u[j] >> shift) & 255u) : 0xFFFFFFFFu;
                unsigned mm = __match_any_sync(0xFFFFFFFFu, bin);
                if (ok && lane == (__ffs(mm) - 1))
                    atomicAdd(&s_cnt[bin], (unsigned)__popc(mm));
            }
        }
        if (tid < tail) {
            unsigned v = __float_as_uint(mine[P4 * 4 + tid]);
            if ((v & hm) == (pref & hm))
                atomicAdd(&s_cnt[(v >> shift) & 255u], 1u);
        }
        __syncthreads();
        if (tid == 0) {
            int k = s_k;
            int cum = 0;
            unsigned g = 0;
            for (int d = 255; d >= 0; d--) {
                int c = (int)s_cnt[d];
                if (cum + c >= k) { g = (unsigned)d; s_k = k - cum; break; }
                cum += c;
            }
            s_prefix = pref | (g << shift);
        }
        __syncthreads();
    }

    unsigned thr = s_prefix;
    double sum = 0.0;
    for (int i = tid; i < P4; i += SEL_THREADS) {
        float4 v = mine4[i];
        if (__float_as_uint(v.x) > thr) sum += (double)v.x;
        if (__float_as_uint(v.y) > thr) sum += (double)v.y;
        if (__float_as_uint(v.z) > thr) sum += (double)v.z;
        if (__float_as_uint(v.w) > thr) sum += (double)v.w;
    }
    if (tid < tail) {
        float f = mine[P4 * 4 + tid];
        if (__float_as_uint(f) > thr) sum += (double)f;
    }
    if (tid == 0) sum += (double)s_k * (double)__uint_as_float(thr);
    s_sum[tid] = sum;
    __syncthreads();
    #pragma unroll
    for (int o = SEL_THREADS / 2; o > 0; o >>= 1) {
        if (tid < o) s_sum[tid] += s_sum[tid + o];
        __syncthreads();
    }
    if (tid == 0) atomicAdd(&g_lossc_part[b & (NSTRIPE - 1)], s_sum[0]);
}

// ---------------- finalize (parallel reduce of striped partials) ------------
__global__ void k_final(float* out, int B) {
    __shared__ double s_l[NSTRIPE];
    __shared__ double s_c[NSTRIPE];
    __shared__ int    s_n[64];
    int tid = threadIdx.x;
    s_l[tid] = g_lossl_part[tid];
    s_c[tid] = g_lossc_part[tid];
    s_n[tid & 63] = 0;
    __syncthreads();
    if (tid < B) s_n[tid] = g_num_pos[tid];
    __syncthreads();
    #pragma unroll
    for (int o = NSTRIPE / 2; o > 0; o >>= 1) {
        if (tid < o) { s_l[tid] += s_l[tid + o]; s_c[tid] += s_c[tid + o]; }
        if (o <= 32 && tid < o) s_n[tid] += s_n[tid + o];
        __syncthreads();
    }
    if (tid == 0) {
        int n = s_n[0];
        double nn = (n < 1) ? 1.0 : (double)n;
        out[0] = (float)(s_l[0] / nn);
        out[1] = (float)(s_c[0] / nn);
    }
}

// ---------------- launch ----------------------------------------------------
extern "C" void kernel_launch(void* const* d_in, const int* in_sizes, int n_in,
                              void* d_out, int out_size) {
    const float* loc     = (const float*)d_in[0];
    const float* conf    = (const float*)d_in[1];
    const float* priors  = (const float*)d_in[2];
    const float* tboxes  = (const float*)d_in[3];
    const int*   tlabels = (const int*)  d_in[4];
    float* out = (float*)d_out;

    int P  = in_sizes[2] / 4;
    int B  = in_sizes[0] / (4 * P);
    int T  = in_sizes[4] / B;
    int C  = (int)((long long)in_sizes[1] / ((long long)B * P));
    int BP = B * P;

    // 1. init scratch accumulators
    {
        int n = B * T;
        if (n < NSTRIPE) n = NSTRIPE;
        k_init<<<(n + 255) / 256, 256>>>(B, T);
    }
    bool fast = (C == 81);
    int mbx = (P + 255) / 256;
    int matchBlocks = mbx * B;
    if (fast) {
        // 2. fused matching + logsumexp (independent work, co-resident overlap)
        long long warps = ((long long)BP + 3) / 4;
        long long lseBlocks = (warps + 7) / 8;         // 8 warps / block
        k_fused<<<(unsigned)(matchBlocks + lseBlocks), 256>>>(
            priors, tboxes, conf, P, T, BP, matchBlocks, mbx);
    } else {
        k_fused<<<dim3(matchBlocks), 256>>>(priors, tboxes, conf, P, T, BP,
                                            matchBlocks, mbx);
    }
    // 3. force-match best prior per gt (prefetched loads)
    k_force<<<(B + 63) / 64, 64>>>(B, P, T);
    // 4. ce epilogue
    if (fast) {
        dim3 grid(mbx, B);
        k_post<<<grid, 256>>>(conf, loc, priors, tboxes, tlabels, P, C, T);
    } else {
        long long total_warps = (long long)BP;
        long long blocks = (total_warps + 7) / 8;
        k_ce_gen<<<(unsigned)blocks, 256>>>(conf, loc, priors, tboxes, tlabels,
                                            B, P, C, T);
    }
    // 5. per-batch hard-negative top-k sum
    k_select<<<B, SEL_THREADS>>>(P);
    // 6. finalize
    k_final<<<1, NSTRIPE>>>(out, B);
}